// round 1
// baseline (speedup 1.0000x reference)
#include <cuda_runtime.h>
#include <math.h>

// Problem constants
#define B_DIM   4096
#define N_GEN   512
#define F_GEN   64
#define EMB     16
#define OUT_ROW 1025          // 2*N_GEN + 1

#define THREADS    128
#define TILE_ROWS  256        // n-rows per tile (2 tiles cover N_GEN)
#define ROW_F2     33         // padded row stride in float2 units (66 floats)

typedef unsigned long long u64;

__device__ __forceinline__ u64 pack2(float lo, float hi) {
    u64 r;
    asm("mov.b64 %0, {%1, %2};" : "=l"(r) : "f"(lo), "f"(hi));
    return r;
}
__device__ __forceinline__ void unpack2(float& lo, float& hi, u64 v) {
    asm("mov.b64 {%0, %1}, %2;" : "=f"(lo), "=f"(hi) : "l"(v));
}
// Packed fp32x2 FMA (Blackwell FFMA2): exact fp32 semantics, 2x FMA throughput.
#define FMA2(acc, a, b) asm("fma.rn.f32x2 %0, %1, %2, %0;" : "+l"(acc) : "l"(a), "l"(b))

// smem layout (floats):
//   [0, 16896)            X tile: 256 rows x 33 float2 (stride 66 floats, padded)
//   [16896, 17920)        W pairs: 512 u64 (W[f][2e],W[f][2e+1])
//   [17920, 17952)        reduction scratch
#define SM_X_F2    (TILE_ROWS * ROW_F2)        // 8448 float2
#define SM_W_OFF   (SM_X_F2 * 2)               // 16896 floats
#define SM_RED_OFF (SM_W_OFF + 1024)           // 17920 floats
#define SM_FLOATS  (SM_RED_OFF + 32)           // 17952 floats = 71808 B

__global__ void __launch_bounds__(THREADS)
fused_model_kernel(const float* __restrict__ x_gen,
                   const float* __restrict__ W_gen,
                   const float* __restrict__ b_gen,
                   const float* __restrict__ W_val,
                   const float* __restrict__ b_val,
                   const float* __restrict__ param,
                   const float* __restrict__ high,
                   float* __restrict__ out)
{
    const int b = blockIdx.x;
    const int t = threadIdx.x;

    extern __shared__ float sm[];
    float2* sX   = reinterpret_cast<float2*>(sm);
    u64*    sW   = reinterpret_cast<u64*>(sm + SM_W_OFF);
    float*  sred = sm + SM_RED_OFF;

    // ---- Stage W_gen into smem as e-pair u64s: sW[f*8 + ep] = (W[f][2ep], W[f][2ep+1])
    {
        const u64* Wg = reinterpret_cast<const u64*>(W_gen);
        #pragma unroll
        for (int k = 0; k < 4; k++) sW[t + THREADS * k] = Wg[t + THREADS * k];
    }

    // ---- Action head: out[b, 0..1023], batch-independent, coalesced scalar stores
    {
        const float s0 = 1.0f / (1.0f + expf(-param[0]));
        const float s1 = 0.5f / (1.0f + expf(-param[1]));
        float* orow = out + (size_t)b * OUT_ROW;
        #pragma unroll
        for (int j = 0; j < 8; j++) {
            int i = t + THREADS * j;            // 0..1023
            int n = i >> 1;
            float h = __ldg(&high[n]);
            orow[i] = (i & 1) ? s1 * h : s0 * h;
        }
    }

    // ---- Bias pairs (accumulator init => free bias add)
    u64 bias[8];
    #pragma unroll
    for (int ep = 0; ep < 8; ep++) bias[ep] = pack2(b_gen[2 * ep], b_gen[2 * ep + 1]);

    float vpart = 0.0f;
    const float4* gx = reinterpret_cast<const float4*>(x_gen + (size_t)b * N_GEN * F_GEN);

    #pragma unroll 1
    for (int tile = 0; tile < 2; tile++) {
        __syncthreads();   // previous tile's smem fully consumed

        // ---- Load tile: 256 rows x 64 floats = 4096 float4, fully contiguous in gmem.
        const float4* gt = gx + tile * (TILE_ROWS * F_GEN / 4);
        #pragma unroll
        for (int k = 0; k < 32; k++) {
            int v = t + THREADS * k;            // float4 index within tile
            float4 d = gt[v];
            int row = v >> 4;                   // 16 float4 per row
            int f4  = v & 15;
            float2* dst = sX + row * ROW_F2 + f4 * 2;
            dst[0] = make_float2(d.x, d.y);
            dst[1] = make_float2(d.z, d.w);
        }
        __syncthreads();

        // ---- Compute: thread owns rows r0=t, r1=t+128 (amortizes W broadcast loads 2x)
        u64 acc0[8], acc1[8];
        #pragma unroll
        for (int ep = 0; ep < 8; ep++) { acc0[ep] = bias[ep]; acc1[ep] = bias[ep]; }

        const float2* x0 = sX + t * ROW_F2;
        const float2* x1 = sX + (t + THREADS) * ROW_F2;

        #pragma unroll 4
        for (int f2 = 0; f2 < 32; f2++) {
            float2 xa = x0[f2];
            float2 xb = x1[f2];
            u64 a0 = pack2(xa.x, xa.x);
            u64 a1 = pack2(xa.y, xa.y);
            u64 c0 = pack2(xb.x, xb.x);
            u64 c1 = pack2(xb.y, xb.y);
            const u64* w = sW + f2 * 16;        // f = 2*f2 at +ep, f = 2*f2+1 at +8+ep
            #pragma unroll
            for (int ep = 0; ep < 8; ep++) {
                u64 w0 = w[ep];
                u64 w1 = w[ep + 8];
                FMA2(acc0[ep], a0, w0);
                FMA2(acc0[ep], a1, w1);
                FMA2(acc1[ep], c0, w0);
                FMA2(acc1[ep], c1, w1);
            }
        }

        // ---- Epilogue: relu + dot with W_val (W_val is L2-resident)
        const int n0 = tile * TILE_ROWS + t;
        const int n1 = tile * TILE_ROWS + t + THREADS;
        const float* wv0 = W_val + n0 * EMB;
        const float* wv1 = W_val + n1 * EMB;
        #pragma unroll
        for (int ep = 0; ep < 8; ep++) {
            float z0, z1, z2, z3;
            unpack2(z0, z1, acc0[ep]);
            unpack2(z2, z3, acc1[ep]);
            vpart += fmaxf(z0, 0.0f) * __ldg(&wv0[2 * ep])
                   + fmaxf(z1, 0.0f) * __ldg(&wv0[2 * ep + 1]);
            vpart += fmaxf(z2, 0.0f) * __ldg(&wv1[2 * ep])
                   + fmaxf(z3, 0.0f) * __ldg(&wv1[2 * ep + 1]);
        }
    }

    // ---- Deterministic block reduction of vpart (4 warps)
    #pragma unroll
    for (int o = 16; o > 0; o >>= 1)
        vpart += __shfl_down_sync(0xffffffff, vpart, o);
    if ((t & 31) == 0) sred[t >> 5] = vpart;
    __syncthreads();
    if (t == 0) {
        float v = ((sred[0] + sred[1]) + (sred[2] + sred[3])) + b_val[0];
        out[(size_t)b * OUT_ROW + 1024] = v;
    }
}

extern "C" void kernel_launch(void* const* d_in, const int* in_sizes, int n_in,
                              void* d_out, int out_size)
{
    const float* x_gen = (const float*)d_in[0];
    const float* W_gen = (const float*)d_in[1];
    const float* b_gen = (const float*)d_in[2];
    const float* W_val = (const float*)d_in[3];
    const float* b_val = (const float*)d_in[4];
    const float* param = (const float*)d_in[5];
    const float* high  = (const float*)d_in[6];
    float* out = (float*)d_out;

    const int smem_bytes = SM_FLOATS * sizeof(float);   // 71808 B
    static bool attr_set = false;
    if (!attr_set) {
        cudaFuncSetAttribute(fused_model_kernel,
                             cudaFuncAttributeMaxDynamicSharedMemorySize, smem_bytes);
        attr_set = true;
    }

    fused_model_kernel<<<B_DIM, THREADS, smem_bytes>>>(
        x_gen, W_gen, b_gen, W_val, b_val, param, high, out);
}

// round 3
// speedup vs baseline: 1.0394x; 1.0394x over previous
#include <cuda_runtime.h>
#include <math.h>

// Problem constants
#define B_DIM   4096
#define N_GEN   512
#define F_GEN   64
#define EMB     16
#define OUT_ROW 1025          // 2*N_GEN + 1

#define THREADS 128
#define CHUNK_F 16            // f-values per chunk
#define HROWS   256           // n-rows per half
#define NSTEPS  8             // 2 halves x 4 f-chunks

typedef unsigned long long u64;

__device__ __forceinline__ u64 pack_dup(float x) {
    u64 r;
    asm("mov.b64 %0, {%1, %1};" : "=l"(r) : "f"(x));
    return r;
}
__device__ __forceinline__ void unpack2(float& lo, float& hi, u64 v) {
    asm("mov.b64 {%0, %1}, %2;" : "=f"(lo), "=f"(hi) : "l"(v));
}
// Packed fp32x2 FMA (Blackwell FFMA2): exact fp32 semantics, 2x FMA throughput.
#define FMA2(acc, a, b) asm("fma.rn.f32x2 %0, %1, %2, %0;" : "+l"(acc) : "l"(a), "l"(b))

__device__ __forceinline__ void cp16(void* smem_dst, const void* gsrc) {
    unsigned s = (unsigned)__cvta_generic_to_shared(smem_dst);
    asm volatile("cp.async.ca.shared.global [%0], [%1], 16;" :: "r"(s), "l"(gsrc));
}
#define CP_COMMIT() asm volatile("cp.async.commit_group;")
#define CP_WAIT(n)  asm volatile("cp.async.wait_group %0;" :: "n"(n))

// Per-step gmem base: half h covers rows h*256..h*256+255, chunk c covers f = c*16..c*16+15
__device__ __forceinline__ const float* step_base(const float* gx, int s) {
    return gx + (s >> 2) * (HROWS * F_GEN) + (s & 3) * CHUNK_F;
}

__device__ __forceinline__ void issue_tile(float* sbuf, const float* gbase, int t) {
    #pragma unroll
    for (int k = 0; k < 8; k++) {
        int idx = t + THREADS * k;          // 0..1023 float4 slots
        int r = idx >> 2, j = idx & 3;
        int p = j ^ ((r >> 1) & 3);         // bank swizzle
        cp16(&sbuf[r * CHUNK_F + p * 4], gbase + r * F_GEN + j * 4);
    }
}

__global__ void __launch_bounds__(THREADS, 6)
fused_model_kernel(const float* __restrict__ x_gen,
                   const float* __restrict__ W_gen,
                   const float* __restrict__ b_gen,
                   const float* __restrict__ W_val,
                   const float* __restrict__ b_val,
                   const float* __restrict__ param,
                   const float* __restrict__ high,
                   float* __restrict__ out)
{
    // x chunk buffers: 256 rows x 16 floats, unpadded (64B/row), XOR-swizzled.
    __shared__ float sX[2][HROWS * CHUNK_F];          // 2 x 16KB
    __shared__ __align__(16) u64 sW[F_GEN * EMB / 2]; // 512 u64 = 4KB
    __shared__ float sred[32];

    const int b = blockIdx.x;
    const int t = threadIdx.x;

    const float* gx = x_gen + (size_t)b * N_GEN * F_GEN;

    // ---- Preload step 0 (half 0, chunk 0) as early as possible
    issue_tile(sX[0], step_base(gx, 0), t);
    CP_COMMIT();

    // ---- Stage W_gen (row-major [64,16]; u64 pairs = adjacent emb values)
    {
        const u64* Wg = reinterpret_cast<const u64*>(W_gen);
        #pragma unroll
        for (int k = 0; k < 4; k++) sW[t + THREADS * k] = Wg[t + THREADS * k];
    }

    // ---- Action head: out[b, 0..1023], batch-independent, coalesced
    {
        const float s0 = 1.0f / (1.0f + expf(-param[0]));
        const float s1 = 0.5f / (1.0f + expf(-param[1]));
        float* orow = out + (size_t)b * OUT_ROW;
        #pragma unroll
        for (int j = 0; j < 8; j++) {
            int i = t + THREADS * j;            // 0..1023
            float h = __ldg(&high[i >> 1]);
            orow[i] = (i & 1) ? s1 * h : s0 * h;
        }
    }

    // ---- Bias pairs for accumulator init (free bias add)
    u64 bias[8];
    {
        const u64* bg = reinterpret_cast<const u64*>(b_gen);
        #pragma unroll
        for (int k = 0; k < 8; k++) bias[k] = bg[k];
    }

    u64 acc0[8], acc1[8];
    float vpart = 0.0f;
    const int sw = (t >> 1) & 3;    // matches store swizzle for rows t and t+128

    // ---- Main pipeline: 8 steps (2 n-halves x 4 f-chunks), double-buffered cp.async
    #pragma unroll
    for (int s = 0; s < NSTEPS; s++) {
        const int c   = s & 3;      // f-chunk within half
        const int buf = s & 1;

        if (s < NSTEPS - 1) {
            issue_tile(sX[buf ^ 1], step_base(gx, s + 1), t);
            CP_COMMIT();
            CP_WAIT(1);             // current step's tile done
        } else {
            CP_WAIT(0);
        }
        __syncthreads();

        if (c == 0) {               // new n-half: reset accumulators to bias
            #pragma unroll
            for (int k = 0; k < 8; k++) { acc0[k] = bias[k]; acc1[k] = bias[k]; }
        }

        const float4* x0 = reinterpret_cast<const float4*>(&sX[buf][t * CHUNK_F]);
        const float4* x1 = reinterpret_cast<const float4*>(&sX[buf][(t + THREADS) * CHUNK_F]);
        const ulonglong2* sW2 = reinterpret_cast<const ulonglong2*>(sW);

        #pragma unroll
        for (int j = 0; j < 4; j++) {
            float4 xa = x0[j ^ sw];
            float4 xb = x1[j ^ sw];
            float av[4] = {xa.x, xa.y, xa.z, xa.w};
            float bv[4] = {xb.x, xb.y, xb.z, xb.w};
            const int fbase = c * CHUNK_F + j * 4;
            #pragma unroll
            for (int ff = 0; ff < 4; ff++) {
                u64 a  = pack_dup(av[ff]);
                u64 bb = pack_dup(bv[ff]);
                const ulonglong2* w = sW2 + (fbase + ff) * 4;
                #pragma unroll
                for (int q = 0; q < 4; q++) {
                    ulonglong2 wp = w[q];       // LDS.128 broadcast: emb 4q..4q+3 of row f
                    FMA2(acc0[2 * q],     a,  wp.x);
                    FMA2(acc0[2 * q + 1], a,  wp.y);
                    FMA2(acc1[2 * q],     bb, wp.x);
                    FMA2(acc1[2 * q + 1], bb, wp.y);
                }
            }
        }

        if (c == 3) {               // half complete: relu + dot with W_val
            const int half = s >> 2;
            const int n0 = half * HROWS + t;
            const int n1 = half * HROWS + t + THREADS;
            const float4* wv = reinterpret_cast<const float4*>(W_val);
            #pragma unroll
            for (int q = 0; q < 4; q++) {
                float4 w0 = __ldg(&wv[n0 * 4 + q]);
                float4 w1 = __ldg(&wv[n1 * 4 + q]);
                float z0, z1, z2, z3;
                unpack2(z0, z1, acc0[2 * q]);
                unpack2(z2, z3, acc0[2 * q + 1]);
                vpart += fmaxf(z0, 0.0f) * w0.x + fmaxf(z1, 0.0f) * w0.y
                       + fmaxf(z2, 0.0f) * w0.z + fmaxf(z3, 0.0f) * w0.w;
                unpack2(z0, z1, acc1[2 * q]);
                unpack2(z2, z3, acc1[2 * q + 1]);
                vpart += fmaxf(z0, 0.0f) * w1.x + fmaxf(z1, 0.0f) * w1.y
                       + fmaxf(z2, 0.0f) * w1.z + fmaxf(z3, 0.0f) * w1.w;
            }
        }
        __syncthreads();            // buffer fully consumed before reuse
    }

    // ---- Deterministic block reduction (4 warps)
    #pragma unroll
    for (int o = 16; o > 0; o >>= 1)
        vpart += __shfl_down_sync(0xffffffff, vpart, o);
    if ((t & 31) == 0) sred[t >> 5] = vpart;
    __syncthreads();
    if (t == 0) {
        float v = ((sred[0] + sred[1]) + (sred[2] + sred[3])) + b_val[0];
        out[(size_t)b * OUT_ROW + 1024] = v;
    }
}

extern "C" void kernel_launch(void* const* d_in, const int* in_sizes, int n_in,
                              void* d_out, int out_size)
{
    const float* x_gen = (const float*)d_in[0];
    const float* W_gen = (const float*)d_in[1];
    const float* b_gen = (const float*)d_in[2];
    const float* W_val = (const float*)d_in[3];
    const float* b_val = (const float*)d_in[4];
    const float* param = (const float*)d_in[5];
    const float* high  = (const float*)d_in[6];
    float* out = (float*)d_out;

    fused_model_kernel<<<B_DIM, THREADS>>>(
        x_gen, W_gen, b_gen, W_val, b_val, param, high, out);
}

// round 4
// speedup vs baseline: 2.2279x; 2.1436x over previous
#include <cuda_runtime.h>
#include <math.h>

#define B_DIM   4096
#define N_GENN  512
#define F_GEN   64
#define EMB     16
#define OUT_ROW 1025
#define THREADS 128
#define CH_ROWS 64            // x rows per staged chunk (16KB)
#define NCHUNK  8

__device__ __forceinline__ unsigned f2tf32(float x) {
    unsigned r; asm("cvt.rna.tf32.f32 %0, %1;" : "=r"(r) : "f"(x)); return r;
}

__device__ __forceinline__ void mma_tf32(float c[4], const unsigned a[4],
                                         unsigned b0, unsigned b1) {
    asm volatile(
        "mma.sync.aligned.m16n8k8.row.col.f32.tf32.tf32.f32 "
        "{%0,%1,%2,%3}, {%4,%5,%6,%7}, {%8,%9}, {%0,%1,%2,%3};"
        : "+f"(c[0]), "+f"(c[1]), "+f"(c[2]), "+f"(c[3])
        : "r"(a[0]), "r"(a[1]), "r"(a[2]), "r"(a[3]), "r"(b0), "r"(b1));
}

__device__ __forceinline__ void ldsm4(unsigned r[4], unsigned addr) {
    asm volatile("ldmatrix.sync.aligned.m8n8.x4.shared.b16 {%0,%1,%2,%3}, [%4];"
                 : "=r"(r[0]), "=r"(r[1]), "=r"(r[2]), "=r"(r[3]) : "r"(addr));
}

__device__ __forceinline__ void cp16(void* smem_dst, const void* gsrc) {
    unsigned s = (unsigned)__cvta_generic_to_shared(smem_dst);
    asm volatile("cp.async.cg.shared.global [%0], [%1], 16;" :: "r"(s), "l"(gsrc));
}
#define CP_COMMIT() asm volatile("cp.async.commit_group;")
#define CP_WAIT(n)  asm volatile("cp.async.wait_group %0;" :: "n"(n))

// Stage one 64-row x chunk (64 rows x 64 floats), 16B-unit XOR swizzle: unit j of
// row r lands at slot j^(r&7). Conflict-free for stores and ldmatrix gathers.
__device__ __forceinline__ void issue_chunk(float* sbuf, const float* gbase, int t) {
    #pragma unroll
    for (int k = 0; k < 8; k++) {
        int idx = t + THREADS * k;          // 0..1023 16B units
        int r = idx >> 4, j = idx & 15;
        int slot = j ^ (r & 7);
        cp16(&sbuf[r * 64 + slot * 4], gbase + r * 64 + j * 4);
    }
}

__global__ void __launch_bounds__(THREADS, 4)
fused_model_kernel(const float* __restrict__ x_gen,
                   const float* __restrict__ W_gen,
                   const float* __restrict__ b_gen,
                   const float* __restrict__ W_val,
                   const float* __restrict__ b_val,
                   const float* __restrict__ param,
                   const float* __restrict__ high,
                   float* __restrict__ out)
{
    __shared__ __align__(1024) float sX[2][CH_ROWS * F_GEN];   // 2 x 16KB
    __shared__ float sred[32];

    const int b    = blockIdx.x;
    const int t    = threadIdx.x;
    const int warp = t >> 5;
    const int lane = t & 31;

    const float* gx = x_gen + (size_t)b * N_GENN * F_GEN;

    // ---- Preload chunk 0 immediately
    issue_chunk(sX[0], gx, t);
    CP_COMMIT();

    // ---- Action head: out[b, 0..1023] (batch-independent, coalesced)
    {
        const float s0 = 1.0f / (1.0f + expf(-param[0]));
        const float s1 = 0.5f / (1.0f + expf(-param[1]));
        float* orow = out + (size_t)b * OUT_ROW;
        #pragma unroll
        for (int j = 0; j < 8; j++) {
            int i = t + THREADS * j;
            float h = __ldg(&high[i >> 1]);
            orow[i] = (i & 1) ? s1 * h : s0 * h;
        }
    }

    // ---- B fragments (W_gen [64,16] row-major), hi/lo tf32 split, in registers.
    // b0 -> W[k=(lane&3)+8ks][n=(lane>>2)+8nt], b1 -> same with k+4.
    unsigned bhi[2][8][2], blo[2][8][2];
    {
        const int kk = lane & 3, nn = lane >> 2;
        #pragma unroll
        for (int nt = 0; nt < 2; nt++)
            #pragma unroll
            for (int ks = 0; ks < 8; ks++)
                #pragma unroll
                for (int h = 0; h < 2; h++) {
                    float w = __ldg(&W_gen[(kk + 4 * h + 8 * ks) * EMB + nn + 8 * nt]);
                    unsigned whi = f2tf32(w);
                    bhi[nt][ks][h] = whi;
                    blo[nt][ks][h] = f2tf32(w - __uint_as_float(whi));
                }
    }

    // ---- Bias values for this thread's C columns: n = 2*(lane&3) + {0,1} + 8*nt
    float bias[2][2];
    #pragma unroll
    for (int nt = 0; nt < 2; nt++) {
        bias[nt][0] = __ldg(&b_gen[2 * (lane & 3) + 8 * nt]);
        bias[nt][1] = __ldg(&b_gen[2 * (lane & 3) + 8 * nt + 1]);
    }

    // ldmatrix addressing: lanes 0-15 -> rows 0-15 (k-low 16B unit),
    // lanes 16-31 -> rows 0-15 (k-high unit). Fixed per-thread parts:
    const int row_local = warp * 16 + (lane & 15);     // row within chunk
    const int hiu       = lane >> 4;                   // 0/1: low/high 16B unit
    const int rxor      = row_local & 7;

    float vpart = 0.0f;

    #pragma unroll 1
    for (int ch = 0; ch < NCHUNK; ch++) {
        const int buf = ch & 1;
        if (ch < NCHUNK - 1) {
            issue_chunk(sX[buf ^ 1], gx + (ch + 1) * CH_ROWS * F_GEN, t);
            CP_COMMIT();
            CP_WAIT(1);
        } else {
            CP_WAIT(0);
        }
        __syncthreads();

        // C accumulators: [nt][k-parity][4]. Bias goes into parity 0 only.
        float c[2][2][4];
        #pragma unroll
        for (int nt = 0; nt < 2; nt++) {
            c[nt][0][0] = c[nt][0][2] = bias[nt][0];
            c[nt][0][1] = c[nt][0][3] = bias[nt][1];
            c[nt][1][0] = c[nt][1][1] = c[nt][1][2] = c[nt][1][3] = 0.0f;
        }

        const unsigned sbase =
            (unsigned)__cvta_generic_to_shared(&sX[buf][0]) + row_local * 256;

        #pragma unroll
        for (int ks = 0; ks < 8; ks++) {
            unsigned raw[4];
            ldsm4(raw, sbase + (((2 * ks + hiu) ^ rxor) << 4));

            unsigned ahi[4], alo[4];
            #pragma unroll
            for (int j = 0; j < 4; j++) {
                float x = __uint_as_float(raw[j]);
                ahi[j] = f2tf32(x);
                alo[j] = f2tf32(x - __uint_as_float(ahi[j]));
            }
            const int p = ks & 1;
            #pragma unroll
            for (int nt = 0; nt < 2; nt++) {
                mma_tf32(c[nt][p], alo, bhi[nt][ks][0], bhi[nt][ks][1]);
                mma_tf32(c[nt][p], ahi, blo[nt][ks][0], blo[nt][ks][1]);
                mma_tf32(c[nt][p], ahi, bhi[nt][ks][0], bhi[nt][ks][1]);
            }
        }

        // ---- Epilogue for this m-tile: relu + dot with W_val
        const int r1 = ch * CH_ROWS + warp * 16 + (lane >> 2);   // global n-row
        const int r2 = r1 + 8;
        #pragma unroll
        for (int nt = 0; nt < 2; nt++) {
            const int n0 = 2 * (lane & 3) + 8 * nt;
            float2 w1 = __ldg(reinterpret_cast<const float2*>(W_val + r1 * EMB + n0));
            float2 w2 = __ldg(reinterpret_cast<const float2*>(W_val + r2 * EMB + n0));
            float z0 = c[nt][0][0] + c[nt][1][0];
            float z1 = c[nt][0][1] + c[nt][1][1];
            float z2 = c[nt][0][2] + c[nt][1][2];
            float z3 = c[nt][0][3] + c[nt][1][3];
            vpart += fmaxf(z0, 0.0f) * w1.x + fmaxf(z1, 0.0f) * w1.y
                   + fmaxf(z2, 0.0f) * w2.x + fmaxf(z3, 0.0f) * w2.y;
        }
        __syncthreads();        // chunk buffer fully consumed before reuse
    }

    // ---- Deterministic block reduction (4 warps)
    #pragma unroll
    for (int o = 16; o > 0; o >>= 1)
        vpart += __shfl_down_sync(0xffffffff, vpart, o);
    if (lane == 0) sred[warp] = vpart;
    __syncthreads();
    if (t == 0) {
        float v = ((sred[0] + sred[1]) + (sred[2] + sred[3])) + b_val[0];
        out[(size_t)b * OUT_ROW + 1024] = v;
    }
}

extern "C" void kernel_launch(void* const* d_in, const int* in_sizes, int n_in,
                              void* d_out, int out_size)
{
    const float* x_gen = (const float*)d_in[0];
    const float* W_gen = (const float*)d_in[1];
    const float* b_gen = (const float*)d_in[2];
    const float* W_val = (const float*)d_in[3];
    const float* b_val = (const float*)d_in[4];
    const float* param = (const float*)d_in[5];
    const float* high  = (const float*)d_in[6];
    float* out = (float*)d_out;

    fused_model_kernel<<<B_DIM, THREADS>>>(
        x_gen, W_gen, b_gen, W_val, b_val, param, high, out);
}

// round 5
// speedup vs baseline: 2.2753x; 1.0213x over previous
#include <cuda_runtime.h>
#include <math.h>

#define B_DIM   4096
#define N_GENN  512
#define F_GEN   64
#define EMB     16
#define OUT_ROW 1025
#define THREADS 128
#define CH_ROWS 64            // x rows per staged chunk (16KB)
#define NCHUNK  8
#define STAGES  3

// Dekker split without CVT: hi = top-11-mantissa-bit truncation (exactly tf32),
// lo = x - hi (exact in fp32; MMA's implicit tf32 truncation of lo is ~2^-21 rel).
__device__ __forceinline__ unsigned split_hi(float x) {
    return __float_as_uint(x) & 0xFFFFE000u;
}

__device__ __forceinline__ void mma_tf32(float c[4], const unsigned a[4],
                                         unsigned b0, unsigned b1) {
    asm volatile(
        "mma.sync.aligned.m16n8k8.row.col.f32.tf32.tf32.f32 "
        "{%0,%1,%2,%3}, {%4,%5,%6,%7}, {%8,%9}, {%0,%1,%2,%3};"
        : "+f"(c[0]), "+f"(c[1]), "+f"(c[2]), "+f"(c[3])
        : "r"(a[0]), "r"(a[1]), "r"(a[2]), "r"(a[3]), "r"(b0), "r"(b1));
}

__device__ __forceinline__ void ldsm4(unsigned r[4], unsigned addr) {
    asm volatile("ldmatrix.sync.aligned.m8n8.x4.shared.b16 {%0,%1,%2,%3}, [%4];"
                 : "=r"(r[0]), "=r"(r[1]), "=r"(r[2]), "=r"(r[3]) : "r"(addr));
}

__device__ __forceinline__ void cp16(void* smem_dst, const void* gsrc) {
    unsigned s = (unsigned)__cvta_generic_to_shared(smem_dst);
    asm volatile("cp.async.cg.shared.global [%0], [%1], 16;" :: "r"(s), "l"(gsrc));
}
#define CP_COMMIT() asm volatile("cp.async.commit_group;")
#define CP_WAIT(n)  asm volatile("cp.async.wait_group %0;" :: "n"(n))

// Stage one 64-row x chunk (64 rows x 64 floats), 16B-unit XOR swizzle: unit j of
// row r lands at slot j^(r&7). Conflict-free for stores and ldmatrix gathers.
__device__ __forceinline__ void issue_chunk(float* sbuf, const float* gbase, int t) {
    #pragma unroll
    for (int k = 0; k < 8; k++) {
        int idx = t + THREADS * k;          // 0..1023 16B units
        int r = idx >> 4, j = idx & 15;
        int slot = j ^ (r & 7);
        cp16(&sbuf[r * 64 + slot * 4], gbase + r * 64 + j * 4);
    }
}

__global__ void __launch_bounds__(THREADS, 4)
fused_model_kernel(const float* __restrict__ x_gen,
                   const float* __restrict__ W_gen,
                   const float* __restrict__ b_gen,
                   const float* __restrict__ W_val,
                   const float* __restrict__ b_val,
                   const float* __restrict__ param,
                   const float* __restrict__ high,
                   float* __restrict__ out)
{
    __shared__ __align__(1024) float sX[STAGES][CH_ROWS * F_GEN];   // 3 x 16KB
    __shared__ float sred[32];

    const int b    = blockIdx.x;
    const int t    = threadIdx.x;
    const int warp = t >> 5;
    const int lane = t & 31;

    const float* gx = x_gen + (size_t)b * N_GENN * F_GEN;

    // ---- Preload chunks 0 and 1 immediately (prefetch distance 2)
    issue_chunk(sX[0], gx, t);
    CP_COMMIT();
    issue_chunk(sX[1], gx + CH_ROWS * F_GEN, t);
    CP_COMMIT();

    // ---- Action head: out[b, 0..1023] (batch-independent, coalesced)
    {
        const float s0 = 1.0f / (1.0f + expf(-param[0]));
        const float s1 = 0.5f / (1.0f + expf(-param[1]));
        float* orow = out + (size_t)b * OUT_ROW;
        #pragma unroll
        for (int j = 0; j < 8; j++) {
            int i = t + THREADS * j;
            float h = __ldg(&high[i >> 1]);
            orow[i] = (i & 1) ? s1 * h : s0 * h;
        }
    }

    // ---- B fragments (W_gen [64,16] row-major), hi/lo split, in registers.
    unsigned bhi[2][8][2], blo[2][8][2];
    {
        const int kk = lane & 3, nn = lane >> 2;
        #pragma unroll
        for (int nt = 0; nt < 2; nt++)
            #pragma unroll
            for (int ks = 0; ks < 8; ks++)
                #pragma unroll
                for (int h = 0; h < 2; h++) {
                    float w = __ldg(&W_gen[(kk + 4 * h + 8 * ks) * EMB + nn + 8 * nt]);
                    unsigned whi = split_hi(w);
                    bhi[nt][ks][h] = whi;
                    blo[nt][ks][h] = __float_as_uint(w - __uint_as_float(whi));
                }
    }

    // ---- Bias values for this thread's C columns: n = 2*(lane&3) + {0,1} + 8*nt
    float bias[2][2];
    #pragma unroll
    for (int nt = 0; nt < 2; nt++) {
        bias[nt][0] = __ldg(&b_gen[2 * (lane & 3) + 8 * nt]);
        bias[nt][1] = __ldg(&b_gen[2 * (lane & 3) + 8 * nt + 1]);
    }

    const int row_local = warp * 16 + (lane & 15);     // row within chunk
    const int hiu       = lane >> 4;                   // 0/1: low/high 16B unit
    const int rxor      = row_local & 7;

    float vpart = 0.0f;

    #pragma unroll 1
    for (int ch = 0; ch < NCHUNK; ch++) {
        const int buf = ch % STAGES;
        if (ch < NCHUNK - 2) {
            issue_chunk(sX[(ch + 2) % STAGES], gx + (ch + 2) * CH_ROWS * F_GEN, t);
            CP_COMMIT();
            CP_WAIT(2);                 // chunk ch's group complete
        } else {
            if (ch == NCHUNK - 2) CP_WAIT(1);
            else                  CP_WAIT(0);
        }
        __syncthreads();

        // C accumulators: [nt][k-parity][4]. Bias into parity 0 only.
        float c[2][2][4];
        #pragma unroll
        for (int nt = 0; nt < 2; nt++) {
            c[nt][0][0] = c[nt][0][2] = bias[nt][0];
            c[nt][0][1] = c[nt][0][3] = bias[nt][1];
            c[nt][1][0] = c[nt][1][1] = c[nt][1][2] = c[nt][1][3] = 0.0f;
        }

        const unsigned sbase =
            (unsigned)__cvta_generic_to_shared(&sX[buf][0]) + row_local * 256;

        #pragma unroll
        for (int ks = 0; ks < 8; ks++) {
            unsigned raw[4];
            ldsm4(raw, sbase + (((2 * ks + hiu) ^ rxor) << 4));

            unsigned ahi[4], alo[4];
            #pragma unroll
            for (int j = 0; j < 4; j++) {
                float x = __uint_as_float(raw[j]);
                ahi[j] = split_hi(x);
                alo[j] = __float_as_uint(x - __uint_as_float(ahi[j]));
            }
            const int p = ks & 1;
            #pragma unroll
            for (int nt = 0; nt < 2; nt++) {
                mma_tf32(c[nt][p], alo, bhi[nt][ks][0], bhi[nt][ks][1]);
                mma_tf32(c[nt][p], ahi, blo[nt][ks][0], blo[nt][ks][1]);
                mma_tf32(c[nt][p], ahi, bhi[nt][ks][0], bhi[nt][ks][1]);
            }
        }

        // ---- Epilogue for this m-tile: relu + dot with W_val
        const int r1 = ch * CH_ROWS + warp * 16 + (lane >> 2);   // global n-row
        const int r2 = r1 + 8;
        #pragma unroll
        for (int nt = 0; nt < 2; nt++) {
            const int n0 = 2 * (lane & 3) + 8 * nt;
            float2 w1 = __ldg(reinterpret_cast<const float2*>(W_val + r1 * EMB + n0));
            float2 w2 = __ldg(reinterpret_cast<const float2*>(W_val + r2 * EMB + n0));
            float z0 = c[nt][0][0] + c[nt][1][0];
            float z1 = c[nt][0][1] + c[nt][1][1];
            float z2 = c[nt][0][2] + c[nt][1][2];
            float z3 = c[nt][0][3] + c[nt][1][3];
            vpart += fmaxf(z0, 0.0f) * w1.x + fmaxf(z1, 0.0f) * w1.y
                   + fmaxf(z2, 0.0f) * w2.x + fmaxf(z3, 0.0f) * w2.y;
        }
        __syncthreads();        // chunk buffer fully consumed before reuse
    }

    // ---- Deterministic block reduction (4 warps)
    #pragma unroll
    for (int o = 16; o > 0; o >>= 1)
        vpart += __shfl_down_sync(0xffffffff, vpart, o);
    if (lane == 0) sred[warp] = vpart;
    __syncthreads();
    if (t == 0) {
        float v = ((sred[0] + sred[1]) + (sred[2] + sred[3])) + b_val[0];
        out[(size_t)b * OUT_ROW + 1024] = v;
    }
}

extern "C" void kernel_launch(void* const* d_in, const int* in_sizes, int n_in,
                              void* d_out, int out_size)
{
    const float* x_gen = (const float*)d_in[0];
    const float* W_gen = (const float*)d_in[1];
    const float* b_gen = (const float*)d_in[2];
    const float* W_val = (const float*)d_in[3];
    const float* b_val = (const float*)d_in[4];
    const float* param = (const float*)d_in[5];
    const float* high  = (const float*)d_in[6];
    float* out = (float*)d_out;

    fused_model_kernel<<<B_DIM, THREADS>>>(
        x_gen, W_gen, b_gen, W_val, b_val, param, high, out);
}